// round 3
// baseline (speedup 1.0000x reference)
#include <cuda_runtime.h>
#include <cstdint>
#include <cstddef>

typedef unsigned long long ull;

#define BATCH 32
#define TT 4
#define NN 512
#define NROWS (BATCH * TT)  // 128
#define KC 32               // k-values per block
#define WW 544              // window width (543 used, padded)
#define PL 8                // planes: t*2 + comp

// FFT results, SoA, duplicated to length 2N so (l-k)%N needs no mod.
__device__ float g_re[NROWS * 2 * NN];
__device__ float g_im[NROWS * 2 * NN];

// ---------------------------------------------------------------------------
// Kernel 1: 512-point complex FFT (Stockham autosort, radix-2), one row/block.
// ---------------------------------------------------------------------------
__global__ void __launch_bounds__(256) fft_kernel(const float* __restrict__ x) {
    __shared__ float2 bufA[NN];
    __shared__ float2 bufB[NN];
    const int row = blockIdx.x;
    const int tid = threadIdx.x;

    const float* xr = x + (size_t)row * NN;
    bufA[tid]       = make_float2(xr[tid], 0.0f);
    bufA[tid + 256] = make_float2(xr[tid + 256], 0.0f);
    __syncthreads();

    float2* X = bufA;
    float2* Y = bufB;
    for (int stage = 0; stage < 9; stage++) {
        const int n = NN >> stage;
        const int m = n >> 1;
        const int s = 1 << stage;
        const int p = tid >> stage;
        const int q = tid & (s - 1);
        float sw, cw;
        __sincosf(-6.283185307179586f * (float)p / (float)n, &sw, &cw);
        const float2 a = X[q + s * p];
        const float2 b = X[q + s * (p + m)];
        Y[q + s * (2 * p)] = make_float2(a.x + b.x, a.y + b.y);
        const float2 dif = make_float2(a.x - b.x, a.y - b.y);
        Y[q + s * (2 * p + 1)] = make_float2(dif.x * cw - dif.y * sw,
                                             dif.x * sw + dif.y * cw);
        __syncthreads();
        float2* t = X; X = Y; Y = t;
    }
    float* gr = g_re + (size_t)row * (2 * NN);
    float* gi = g_im + (size_t)row * (2 * NN);
    for (int i = tid; i < NN; i += 256) {
        const float2 v = X[i];
        gr[i] = v.x; gr[i + NN] = v.x;
        gi[i] = v.y; gi[i + NN] = v.y;
    }
}

// ---------------------------------------------------------------------------
// Kernel 2: bispectrum.  lane -> l-pair (f32x2), loop -> k.
// out[b][0][k][l] = Re, out[b][1][k][l] = Im of mean_t y_k conj(y_l) y_{l-k}.
// ---------------------------------------------------------------------------
__device__ __forceinline__ float2 up2(ull v) {
    float lo, hi;
    asm("mov.b64 {%0, %1}, %2;" : "=f"(lo), "=f"(hi) : "l"(v));
    return make_float2(lo, hi);
}
#define FMA2(d, a, b, c) \
    asm("fma.rn.f32x2 %0, %1, %2, %3;" : "=l"(d) : "l"(a), "l"(b), "l"(c))
#define MUL2(d, a, b) \
    asm("mul.rn.f32x2 %0, %1, %2;" : "=l"(d) : "l"(a), "l"(b))

__device__ __forceinline__ void bstep(
    const float* __restrict__ sW, const float2* __restrict__ sK,
    int kk, int cOff, const ull* BR, const ull* BI,
    float* outR, float* outI)
{
    ull ra, rb, ia, ib;
    #pragma unroll
    for (int t = 0; t < TT; t++) {
        const ull akr = *(const ull*)&sK[(0 * TT + t) * KC + kk];
        const ull aki = *(const ull*)&sK[(1 * TT + t) * KC + kk];
        const ull nkr = *(const ull*)&sK[(2 * TT + t) * KC + kk];
        const ull cr  = *(const ull*)&sW[(2 * t + 0) * 2 * WW + cOff];
        const ull ci  = *(const ull*)&sW[(2 * t + 1) * 2 * WW + cOff];
        ull t1, t2, pr, pi;
        MUL2(t1, aki, BI[t]);  FMA2(pr, akr, BR[t], t1);  // 0.25*(ar*br+ai*bi)
        MUL2(t2, nkr, BI[t]);  FMA2(pi, aki, BR[t], t2);  // 0.25*(ai*br-ar*bi)
        if (t == 0) {
            MUL2(ra, pr, cr); MUL2(rb, pi, ci);
            MUL2(ia, pr, ci); MUL2(ib, pi, cr);
        } else {
            FMA2(ra, pr, cr, ra); FMA2(rb, pi, ci, rb);
            FMA2(ia, pr, ci, ia); FMA2(ib, pi, cr, ib);
        }
    }
    const float2 a = up2(ra), bq = up2(rb), c = up2(ia), d = up2(ib);
    *(float2*)outR = make_float2(a.x - bq.x, a.y - bq.y);
    *(float2*)outI = make_float2(c.x + d.x, c.y + d.y);
}

__global__ void __launch_bounds__(256, 5) bispec_kernel(float* __restrict__ out) {
    __shared__ float  sW[PL * 2 * WW];   // per plane: [0..WW) window, [WW..2WW) +1-shifted
    __shared__ float2 sK[3 * TT * KC];   // 0: .25*akr dup, 1: .25*aki dup, 2: -.25*akr dup

    const int b   = blockIdx.y;
    const int k0  = blockIdx.x * KC;
    const int tid = threadIdx.x;
    const int base = NN - k0 - (KC - 1);

    // Fill window (both base and shifted copies).
    for (int i = tid; i < PL * 2 * WW; i += 256) {
        const int p   = i / (2 * WW);
        const int off = i - p * (2 * WW);
        const int t   = p >> 1;
        const float* g  = (p & 1) ? g_im : g_re;
        const float* gp = g + (size_t)(b * TT + t) * (2 * NN);
        int src = base + (off < WW ? off : off - WW + 1);
        if (src > 2 * NN - 1) src = 2 * NN - 1;   // padding region, unused
        sW[i] = gp[src];
    }
    // Fill pre-packed broadcast y_k tables (scale 1/TT folded in).
    for (int i = tid; i < 3 * TT * KC; i += 256) {
        const int which = i / (TT * KC);
        const int r  = i - which * (TT * KC);
        const int t  = r / KC;
        const int kk = r - t * KC;
        const float* g = (which == 1) ? g_im : g_re;
        float v = 0.25f * g[(size_t)(b * TT + t) * (2 * NN) + k0 + kk];
        if (which == 2) v = -v;
        sK[i] = make_float2(v, v);
    }
    __syncthreads();

    // Per-thread l-pair factor y_l (register-resident for whole kernel).
    const int i2 = tid << 1;
    ull BR[TT], BI[TT];
    #pragma unroll
    for (int t = 0; t < TT; t++) {
        BR[t] = *(const ull*)(g_re + (size_t)(b * TT + t) * (2 * NN) + i2);
        BI[t] = *(const ull*)(g_im + (size_t)(b * TT + t) * (2 * NN) + i2);
    }

    float* outR = out + ((size_t)(b * 2) * NN + k0) * NN + i2;
    float* outI = outR + (size_t)NN * NN;

    // CM pair index j = (KC-1-kk) + i2.  kk even -> j odd -> shifted copy at
    // WW + j - 1; kk odd -> j even -> base copy at j.  Both aligned LDS.64.
    int offS = WW + (KC - 2) + i2;  // even kk
    int offW = (KC - 2) + i2;       // odd kk

    #pragma unroll 2
    for (int e = 0; e < KC; e += 2) {
        bstep(sW, sK, e,     offS, BR, BI, outR, outI);
        outR += NN; outI += NN;
        bstep(sW, sK, e + 1, offW, BR, BI, outR, outI);
        outR += NN; outI += NN;
        offS -= 2; offW -= 2;
    }
}

// ---------------------------------------------------------------------------
extern "C" void kernel_launch(void* const* d_in, const int* in_sizes, int n_in,
                              void* d_out, int out_size) {
    const float* target = (const float*)d_in[0];
    float* out = (float*)d_out;

    fft_kernel<<<NROWS, 256>>>(target);

    dim3 grid(NN / KC, BATCH);   // 16 x 32 = 512 blocks, 256 threads
    bispec_kernel<<<grid, 256>>>(out);

    // Second tuple element: passthrough of target, if the harness expects it.
    const long long src_elems = (long long)BATCH * 2 * NN * NN;  // 16,777,216
    if ((long long)out_size > src_elems) {
        const long long tail = (long long)out_size - src_elems;
        cudaMemcpyAsync(out + src_elems, target,
                        (size_t)tail * sizeof(float),
                        cudaMemcpyDeviceToDevice);
    }
}

// round 4
// speedup vs baseline: 1.4653x; 1.4653x over previous
#include <cuda_runtime.h>
#include <cstdint>
#include <cstddef>

typedef unsigned long long ull;

#define BATCH 32
#define TT 4
#define NN 512
#define NROWS (BATCH * TT)  // 128
#define KC 32               // k-values per block
#define WW 544              // window width per shift copy
#define SMEM_WIN (8 * 4 * WW)           // 17408 floats
#define SMEM_K   (3 * TT * KC * 2)      // 768 floats (float2 dup tables)
#define SMEM_BYTES ((SMEM_WIN + SMEM_K) * 4)

// FFT results, SoA, duplicated to length 2N so (l-k)%N needs no mod.
__device__ float g_re[NROWS * 2 * NN];
__device__ float g_im[NROWS * 2 * NN];

// ---------------------------------------------------------------------------
// Kernel 1: 512-point complex FFT (Stockham autosort, radix-2), one row/block.
// ---------------------------------------------------------------------------
__global__ void __launch_bounds__(256) fft_kernel(const float* __restrict__ x) {
    __shared__ float2 bufA[NN];
    __shared__ float2 bufB[NN];
    const int row = blockIdx.x;
    const int tid = threadIdx.x;

    const float* xr = x + (size_t)row * NN;
    bufA[tid]       = make_float2(xr[tid], 0.0f);
    bufA[tid + 256] = make_float2(xr[tid + 256], 0.0f);
    __syncthreads();

    float2* X = bufA;
    float2* Y = bufB;
    for (int stage = 0; stage < 9; stage++) {
        const int n = NN >> stage;
        const int m = n >> 1;
        const int s = 1 << stage;
        const int p = tid >> stage;
        const int q = tid & (s - 1);
        float sw, cw;
        __sincosf(-6.283185307179586f * (float)p / (float)n, &sw, &cw);
        const float2 a = X[q + s * p];
        const float2 b = X[q + s * (p + m)];
        Y[q + s * (2 * p)] = make_float2(a.x + b.x, a.y + b.y);
        const float2 dif = make_float2(a.x - b.x, a.y - b.y);
        Y[q + s * (2 * p + 1)] = make_float2(dif.x * cw - dif.y * sw,
                                             dif.x * sw + dif.y * cw);
        __syncthreads();
        float2* t = X; X = Y; Y = t;
    }
    float* gr = g_re + (size_t)row * (2 * NN);
    float* gi = g_im + (size_t)row * (2 * NN);
    for (int i = tid; i < NN; i += 256) {
        const float2 v = X[i];
        gr[i] = v.x; gr[i + NN] = v.x;
        gi[i] = v.y; gi[i + NN] = v.y;
    }
}

// ---------------------------------------------------------------------------
// Kernel 2: bispectrum.  Thread tile: 2 quads of l (l=4tx, l=4tx+256), loop k.
// ---------------------------------------------------------------------------
#define FMA2(d, a, b, c) \
    asm("fma.rn.f32x2 %0, %1, %2, %3;" : "=l"(d) : "l"(a), "l"(b), "l"(c))
#define MUL2(d, a, b) \
    asm("mul.rn.f32x2 %0, %1, %2;" : "=l"(d) : "l"(a), "l"(b))
#define ADD2(d, a, b) \
    asm("add.rn.f32x2 %0, %1, %2;" : "=l"(d) : "l"(a), "l"(b))

__global__ void __launch_bounds__(256, 2) bispec_kernel(float* __restrict__ out) {
    extern __shared__ __align__(16) float smem[];
    float* sWin = smem;             // [p][s][i] : p*4*WW + s*WW + i
    float* sK   = smem + SMEM_WIN;  // [which][t][kk] dup float2

    const int tx  = threadIdx.x;           // 0..63  (l quads)
    const int ky  = threadIdx.y;           // 0..3   (kk mod 4)
    const int tid = ky * 64 + tx;
    const int b   = blockIdx.y;
    const int k0  = blockIdx.x * KC;
    const int base = NN - k0 - 31;

    // ---- fill 4-shift window copies: copy_s[p][i] = dup_p[base + i + s] ----
    for (int idx = tid; idx < SMEM_WIN; idx += 256) {
        const int p = idx / (4 * WW);
        const int r = idx - p * (4 * WW);
        const int s = r / WW;
        const int i = r - s * WW;
        int src = base + i + s;
        if (src > 2 * NN - 1) src = 2 * NN - 1;   // unused padding
        const float* g = (p & 1) ? g_im : g_re;
        sWin[idx] = g[(size_t)(b * TT + (p >> 1)) * (2 * NN) + src];
    }
    // ---- y_k tables: 0: .25*re dup, 1: .25*im dup, 2: -.25*re dup ----
    for (int idx = tid; idx < 3 * TT * KC; idx += 256) {
        const int which = idx / (TT * KC);
        const int r = idx - which * (TT * KC);   // t*KC + kk
        const float* g = (which == 1) ? g_im : g_re;
        float v = 0.25f * g[(size_t)(b * TT + r / KC) * (2 * NN) + k0 + (r & (KC - 1))];
        if (which == 2) v = -v;
        sK[idx * 2]     = v;
        sK[idx * 2 + 1] = v;
    }

    // ---- persistent y_l registers: 2 quads x 4t x 2comp x 2 pairs ----
    ull blr[TT][2][2], bli[TT][2][2];
    #pragma unroll
    for (int t = 0; t < TT; t++) {
        const size_t row = (size_t)(b * TT + t) * (2 * NN);
        #pragma unroll
        for (int h = 0; h < 2; h++) {
            const int l = 4 * tx + 256 * h;
            const ulonglong2 vr = *(const ulonglong2*)(g_re + row + l);
            const ulonglong2 vi = *(const ulonglong2*)(g_im + row + l);
            blr[t][h][0] = vr.x; blr[t][h][1] = vr.y;
            bli[t][h][0] = vi.x; bli[t][h][1] = vi.y;
        }
    }
    __syncthreads();

    // thread-fixed shift copy: s = (31-kk)&3 = 3-ky  (kk = 4i+ky)
    const float* winT = sWin + (3 - ky) * WW + 4 * tx + 28;
    const float* kT   = sK + 2 * ky;
    float* outR = out + ((size_t)(b * 2) * NN + (k0 + ky)) * NN + 4 * tx;
    float* outI = outR + (size_t)NN * NN;

    #pragma unroll 2
    for (int i = 0; i < 8; i++) {
        ull a0[2][2], a1[2][2], a2[2][2], a3[2][2];  // [h][q] chains
        #pragma unroll
        for (int t = 0; t < TT; t++) {
            const ull akr = *(const ull*)(kT + (0 * TT * KC + t * KC + 4 * i) * 2);
            const ull aki = *(const ull*)(kT + (1 * TT * KC + t * KC + 4 * i) * 2);
            const ull nkr = *(const ull*)(kT + (2 * TT * KC + t * KC + 4 * i) * 2);
            #pragma unroll
            for (int h = 0; h < 2; h++) {
                const float* wr = winT + (2 * t + 0) * 4 * WW + 256 * h - 4 * i;
                const float* wi = winT + (2 * t + 1) * 4 * WW + 256 * h - 4 * i;
                const ulonglong2 cmr = *(const ulonglong2*)wr;  // LDS.128
                const ulonglong2 cmi = *(const ulonglong2*)wi;  // LDS.128
                #pragma unroll
                for (int q = 0; q < 2; q++) {
                    const ull CR = q ? cmr.y : cmr.x;
                    const ull CI = q ? cmi.y : cmi.x;
                    ull u, v, pr, pi;
                    MUL2(u, aki, bli[t][h][q]);  FMA2(pr, akr, blr[t][h][q], u);
                    MUL2(v, nkr, bli[t][h][q]);  FMA2(pi, aki, blr[t][h][q], v);
                    if (t == 0) {
                        MUL2(a0[h][q], pr, CR); MUL2(a1[h][q], pi, CI);
                        MUL2(a2[h][q], pr, CI); MUL2(a3[h][q], pi, CR);
                    } else {
                        FMA2(a0[h][q], pr, CR, a0[h][q]);
                        FMA2(a1[h][q], pi, CI, a1[h][q]);
                        FMA2(a2[h][q], pr, CI, a2[h][q]);
                        FMA2(a3[h][q], pi, CR, a3[h][q]);
                    }
                }
            }
        }
        #pragma unroll
        for (int h = 0; h < 2; h++) {
            ulonglong2 re4, im4;
            ull n0 = a1[h][0] ^ 0x8000000080000000ULL;
            ull n1 = a1[h][1] ^ 0x8000000080000000ULL;
            ADD2(re4.x, a0[h][0], n0);
            ADD2(re4.y, a0[h][1], n1);
            ADD2(im4.x, a2[h][0], a3[h][0]);
            ADD2(im4.y, a2[h][1], a3[h][1]);
            *(ulonglong2*)(outR + 256 * h) = re4;  // STG.128
            *(ulonglong2*)(outI + 256 * h) = im4;  // STG.128
        }
        outR += 4 * NN;
        outI += 4 * NN;
    }
}

// ---------------------------------------------------------------------------
extern "C" void kernel_launch(void* const* d_in, const int* in_sizes, int n_in,
                              void* d_out, int out_size) {
    const float* target = (const float*)d_in[0];
    float* out = (float*)d_out;

    cudaFuncSetAttribute(bispec_kernel,
                         cudaFuncAttributeMaxDynamicSharedMemorySize,
                         SMEM_BYTES);

    fft_kernel<<<NROWS, 256>>>(target);

    dim3 grid(NN / KC, BATCH);   // 16 x 32 = 512 blocks
    dim3 block(64, 4);           // 256 threads
    bispec_kernel<<<grid, block, SMEM_BYTES>>>(out);

    // Second tuple element: passthrough of target, if the harness expects it.
    const long long src_elems = (long long)BATCH * 2 * NN * NN;  // 16,777,216
    if ((long long)out_size > src_elems) {
        const long long tail = (long long)out_size - src_elems;
        cudaMemcpyAsync(out + src_elems, target,
                        (size_t)tail * sizeof(float),
                        cudaMemcpyDeviceToDevice);
    }
}